// round 8
// baseline (speedup 1.0000x reference)
#include <cuda_runtime.h>
#include <cuda_bf16.h>

// DistMult decoder:
//   out[e] = sigmoid( sum_d x[left[e],d] * R[type[e],d] * x[right[e],d] )
//
// R8: as R7 (8 lanes/edge, 4 edges/group, f32x2 packed FMA, 128 edges/block,
// launch_bounds(256,8) -> 32 regs, int4 smem index staging) plus:
// warp-uniform relation fast path — edge_type is sorted, so ~99.96% of warps
// use a single R-row load instead of 4 (cuts LDG slots + L1 wavefronts).

__device__ int g_idx_is64;

__global__ void detect_idx_dtype(const void* edge_index_raw)
{
    const long long* p = (const long long*)edge_index_raw;
    int is64 = 1;
    #pragma unroll
    for (int i = 0; i < 8; i++) {
        long long v = p[i];
        if (v < 0 || v >= 100000LL) is64 = 0;
    }
    g_idx_is64 = is64;
}

#define PACK2(out_, x_, y_) \
    asm("mov.b64 %0, {%1, %2};" : "=l"(out_) : "f"(x_), "f"(y_))
#define UNPACK2(x_, y_, in_) \
    asm("mov.b64 {%0, %1}, %2;" : "=f"(x_), "=f"(y_) : "l"(in_))
#define MUL2(out_, a_, b_) \
    asm("mul.rn.f32x2 %0, %1, %2;" : "=l"(out_) : "l"(a_), "l"(b_))
#define FMA2(out_, a_, b_, c_) \
    asm("fma.rn.f32x2 %0, %1, %2, %3;" : "=l"(out_) : "l"(a_), "l"(b_), "l"(c_))

// Triple-product partial for one edge on this lane: sum over 4 dims.
__device__ __forceinline__ float triple4(float4 a, float4 c, float4 b)
{
    unsigned long long a0, a1, b0, b1, c0, c1, t, acc;
    PACK2(a0, a.x, a.y); PACK2(a1, a.z, a.w);
    PACK2(b0, b.x, b.y); PACK2(b1, b.z, b.w);
    PACK2(c0, c.x, c.y); PACK2(c1, c.z, c.w);
    MUL2(t, a0, c0);
    MUL2(acc, t, b0);            // acc = a0*c0*b0
    MUL2(t, a1, c1);
    FMA2(acc, t, b1, acc);       // acc += a1*c1*b1
    float lo, hi;
    UNPACK2(lo, hi, acc);
    return lo + hi;
}

__global__ void __launch_bounds__(256, 8) distmult_kernel(
    const float* __restrict__ x,
    const float* __restrict__ R,
    const void* __restrict__ edge_index_raw,
    const void* __restrict__ edge_type_raw,
    float* __restrict__ out,
    int E)
{
    __shared__ int4 s_idx[128];   // (l, r, t, 0) per edge

    const int e0  = blockIdx.x * 128;
    const int tid = threadIdx.x;

    // ---- Stage indices for 128 edges as packed int4 ----
    if (tid < 128) {
        int e = e0 + tid;
        int l = 0, r = 0, t = 0;          // OOB -> row 0 (legal loads)
        if (e < E) {
            if (g_idx_is64) {
                const long long* ei = (const long long*)edge_index_raw;
                const long long* et = (const long long*)edge_type_raw;
                l = (int)__ldg(ei + e);
                r = (int)__ldg(ei + E + e);
                t = (int)__ldg(et + e);
            } else {
                const int* ei = (const int*)edge_index_raw;
                const int* et = (const int*)edge_type_raw;
                l = __ldg(ei + e);
                r = __ldg(ei + E + e);
                t = __ldg(et + e);
            }
        }
        s_idx[tid] = make_int4(l, r, t, 0);
    }
    __syncthreads();

    // ---- Each 8-lane group handles 4 consecutive edges ----
    const int gid = tid >> 3;        // 0..31
    const int sub = tid & 7;
    const int eb  = gid * 4;

    // LDS.128 per edge; broadcast within group, conflict-free across groups.
    const int4 i0 = s_idx[eb + 0];
    const int4 i1 = s_idx[eb + 1];
    const int4 i2 = s_idx[eb + 2];
    const int4 i3 = s_idx[eb + 3];

    const float4* xb = (const float4*)x;
    const float4* Rb = (const float4*)R;

    // 8 independent x-row loads (8 lanes x 16 B = one 128 B line per inst)
    float4 A0 = __ldg(xb + i0.x * 8 + sub);
    float4 B0 = __ldg(xb + i0.y * 8 + sub);
    float4 A1 = __ldg(xb + i1.x * 8 + sub);
    float4 B1 = __ldg(xb + i1.y * 8 + sub);
    float4 A2 = __ldg(xb + i2.x * 8 + sub);
    float4 B2 = __ldg(xb + i2.y * 8 + sub);
    float4 A3 = __ldg(xb + i3.x * 8 + sub);
    float4 B3 = __ldg(xb + i3.y * 8 + sub);

    // Relation rows: edge_type is sorted -> almost every warp is uniform.
    // Warp-coherent branch (uni is warp-uniform by construction).
    const unsigned FULL = 0xffffffffu;
    int t_ref = __shfl_sync(FULL, i0.z, 0);
    bool uni  = __all_sync(FULL,
                  (i0.z == t_ref) & (i1.z == t_ref) &
                  (i2.z == t_ref) & (i3.z == t_ref));

    float4 C0, C1, C2, C3;
    if (uni) {
        C0 = __ldg(Rb + t_ref * 8 + sub);   // one load serves all 4 edges
        C1 = C0; C2 = C0; C3 = C0;
    } else {
        C0 = __ldg(Rb + i0.z * 8 + sub);
        C1 = __ldg(Rb + i1.z * 8 + sub);
        C2 = __ldg(Rb + i2.z * 8 + sub);
        C3 = __ldg(Rb + i3.z * 8 + sub);
    }

    float s0 = triple4(A0, C0, B0);
    float s1 = triple4(A1, C1, B1);
    float s2 = triple4(A2, C2, B2);
    float s3 = triple4(A3, C3, B3);

    // Butterfly reduce over 8 lanes; 4 independent chains interleave.
    s0 += __shfl_xor_sync(FULL, s0, 4);
    s1 += __shfl_xor_sync(FULL, s1, 4);
    s2 += __shfl_xor_sync(FULL, s2, 4);
    s3 += __shfl_xor_sync(FULL, s3, 4);
    s0 += __shfl_xor_sync(FULL, s0, 2);
    s1 += __shfl_xor_sync(FULL, s1, 2);
    s2 += __shfl_xor_sync(FULL, s2, 2);
    s3 += __shfl_xor_sync(FULL, s3, 2);
    s0 += __shfl_xor_sync(FULL, s0, 1);
    s1 += __shfl_xor_sync(FULL, s1, 1);
    s2 += __shfl_xor_sync(FULL, s2, 1);
    s3 += __shfl_xor_sync(FULL, s3, 1);

    // Lanes 0..3 of each group store edges eb+0..eb+3.
    float v = s0;
    if (sub == 1) v = s1;
    if (sub == 2) v = s2;
    if (sub == 3) v = s3;

    const int e = e0 + eb + sub;
    if (sub < 4 && e < E) {
        out[e] = __fdividef(1.0f, 1.0f + __expf(-v));
    }
}

extern "C" void kernel_launch(void* const* d_in, const int* in_sizes, int n_in,
                              void* d_out, int out_size)
{
    int E = out_size;  // one score per edge

    const float* x  = nullptr;
    const float* R  = nullptr;
    const void*  ei = nullptr;
    const void*  et = nullptr;
    for (int i = 0; i < n_in; i++) {
        long long sz = in_sizes[i];
        if      (sz == 2LL * E)      ei = d_in[i];
        else if (sz == (long long)E) et = d_in[i];
        else if (sz == 30848LL)      R  = (const float*)d_in[i];
        else                         x  = (const float*)d_in[i];
    }
    if (!x || !R || !ei || !et) {
        x  = (const float*)d_in[0];
        R  = (const float*)d_in[1];
        ei = d_in[2];
        et = d_in[3];
    }

    detect_idx_dtype<<<1, 1>>>(ei);

    int blocks = (E + 127) / 128;
    distmult_kernel<<<blocks, 256>>>(x, R, ei, et, (float*)d_out, E);
}

// round 9
// speedup vs baseline: 1.3881x; 1.3881x over previous
#include <cuda_runtime.h>
#include <cuda_bf16.h>

// DistMult decoder:
//   out[e] = sigmoid( sum_d x[left[e],d] * R[type[e],d] * x[right[e],d] )
//
// R9: R7 body (8 lanes/edge, 4 edges/group, f32x2 packed FMA, 128 edges/tile,
// launch_bounds(256,8) -> 32 regs, int4 smem index staging, unconditional
// C loads — NO branches between staging and the gather batch), made
// persistent: grid-stride loop over tiles with double-buffered index staging
// to kill wave-transition overhead and overlap consecutive tiles' gathers.

__device__ int g_idx_is64;

__global__ void detect_idx_dtype(const void* edge_index_raw)
{
    const long long* p = (const long long*)edge_index_raw;
    int is64 = 1;
    #pragma unroll
    for (int i = 0; i < 8; i++) {
        long long v = p[i];
        if (v < 0 || v >= 100000LL) is64 = 0;
    }
    g_idx_is64 = is64;
}

#define PACK2(out_, x_, y_) \
    asm("mov.b64 %0, {%1, %2};" : "=l"(out_) : "f"(x_), "f"(y_))
#define UNPACK2(x_, y_, in_) \
    asm("mov.b64 {%0, %1}, %2;" : "=f"(x_), "=f"(y_) : "l"(in_))
#define MUL2(out_, a_, b_) \
    asm("mul.rn.f32x2 %0, %1, %2;" : "=l"(out_) : "l"(a_), "l"(b_))
#define FMA2(out_, a_, b_, c_) \
    asm("fma.rn.f32x2 %0, %1, %2, %3;" : "=l"(out_) : "l"(a_), "l"(b_), "l"(c_))

// Triple-product partial for one edge on this lane: sum over 4 dims.
__device__ __forceinline__ float triple4(float4 a, float4 c, float4 b)
{
    unsigned long long a0, a1, b0, b1, c0, c1, t, acc;
    PACK2(a0, a.x, a.y); PACK2(a1, a.z, a.w);
    PACK2(b0, b.x, b.y); PACK2(b1, b.z, b.w);
    PACK2(c0, c.x, c.y); PACK2(c1, c.z, c.w);
    MUL2(t, a0, c0);
    MUL2(acc, t, b0);            // acc = a0*c0*b0
    MUL2(t, a1, c1);
    FMA2(acc, t, b1, acc);       // acc += a1*c1*b1
    float lo, hi;
    UNPACK2(lo, hi, acc);
    return lo + hi;
}

// Stage indices for one 128-edge tile into s_idx as packed int4.
__device__ __forceinline__ void stage_tile(
    int4* s_idx, int e0, int tid, int E, int is64,
    const void* edge_index_raw, const void* edge_type_raw)
{
    if (tid < 128) {
        int e = e0 + tid;
        int l = 0, r = 0, t = 0;          // OOB -> row 0 (legal loads)
        if (e < E) {
            if (is64) {
                const long long* ei = (const long long*)edge_index_raw;
                const long long* et = (const long long*)edge_type_raw;
                l = (int)__ldg(ei + e);
                r = (int)__ldg(ei + E + e);
                t = (int)__ldg(et + e);
            } else {
                const int* ei = (const int*)edge_index_raw;
                const int* et = (const int*)edge_type_raw;
                l = __ldg(ei + e);
                r = __ldg(ei + E + e);
                t = __ldg(et + e);
            }
        }
        s_idx[tid] = make_int4(l, r, t, 0);
    }
}

__global__ void __launch_bounds__(256, 8) distmult_kernel(
    const float* __restrict__ x,
    const float* __restrict__ R,
    const void* __restrict__ edge_index_raw,
    const void* __restrict__ edge_type_raw,
    float* __restrict__ out,
    int E, int ntiles)
{
    __shared__ int4 s_idx[2][128];   // double-buffered (l, r, t, 0) per edge

    const int tid  = threadIdx.x;
    const int gid  = tid >> 3;       // 0..31 (8-lane group id)
    const int sub  = tid & 7;
    const int eb   = gid * 4;        // first edge slot of this group
    const int is64 = g_idx_is64;

    const float4* xb = (const float4*)x;
    const float4* Rb = (const float4*)R;

    int tile = blockIdx.x;
    int buf  = 0;

    // Prologue: stage first tile.
    stage_tile(s_idx[0], tile * 128, tid, E, is64,
               edge_index_raw, edge_type_raw);
    __syncthreads();

    for (; tile < ntiles; tile += gridDim.x) {
        const int e0 = tile * 128;

        // LDS.128 per edge; broadcast within group, conflict-free across groups.
        const int4 i0 = s_idx[buf][eb + 0];
        const int4 i1 = s_idx[buf][eb + 1];
        const int4 i2 = s_idx[buf][eb + 2];
        const int4 i3 = s_idx[buf][eb + 3];

        // 12 independent row loads (8 lanes x 16 B = one 128 B line per inst)
        float4 A0 = __ldg(xb + i0.x * 8 + sub);
        float4 B0 = __ldg(xb + i0.y * 8 + sub);
        float4 A1 = __ldg(xb + i1.x * 8 + sub);
        float4 B1 = __ldg(xb + i1.y * 8 + sub);
        float4 A2 = __ldg(xb + i2.x * 8 + sub);
        float4 B2 = __ldg(xb + i2.y * 8 + sub);
        float4 A3 = __ldg(xb + i3.x * 8 + sub);
        float4 B3 = __ldg(xb + i3.y * 8 + sub);
        float4 C0 = __ldg(Rb + i0.z * 8 + sub);   // near-uniform (sorted types)
        float4 C1 = __ldg(Rb + i1.z * 8 + sub);
        float4 C2 = __ldg(Rb + i2.z * 8 + sub);
        float4 C3 = __ldg(Rb + i3.z * 8 + sub);

        // Stage NEXT tile's indices into the other buffer (overlaps with the
        // outstanding gathers above; protected by the sync below).
        int next = tile + gridDim.x;
        if (next < ntiles) {
            stage_tile(s_idx[buf ^ 1], next * 128, tid, E, is64,
                       edge_index_raw, edge_type_raw);
        }

        float s0 = triple4(A0, C0, B0);
        float s1 = triple4(A1, C1, B1);
        float s2 = triple4(A2, C2, B2);
        float s3 = triple4(A3, C3, B3);

        // Butterfly reduce over 8 lanes; 4 independent chains interleave.
        const unsigned FULL = 0xffffffffu;
        s0 += __shfl_xor_sync(FULL, s0, 4);
        s1 += __shfl_xor_sync(FULL, s1, 4);
        s2 += __shfl_xor_sync(FULL, s2, 4);
        s3 += __shfl_xor_sync(FULL, s3, 4);
        s0 += __shfl_xor_sync(FULL, s0, 2);
        s1 += __shfl_xor_sync(FULL, s1, 2);
        s2 += __shfl_xor_sync(FULL, s2, 2);
        s3 += __shfl_xor_sync(FULL, s3, 2);
        s0 += __shfl_xor_sync(FULL, s0, 1);
        s1 += __shfl_xor_sync(FULL, s1, 1);
        s2 += __shfl_xor_sync(FULL, s2, 1);
        s3 += __shfl_xor_sync(FULL, s3, 1);

        // Lanes 0..3 of each group store edges eb+0..eb+3.
        float v = s0;
        if (sub == 1) v = s1;
        if (sub == 2) v = s2;
        if (sub == 3) v = s3;

        const int e = e0 + eb + sub;
        if (sub < 4 && e < E) {
            out[e] = __fdividef(1.0f, 1.0f + __expf(-v));
        }

        __syncthreads();   // next-tile staging complete; old buffer reusable
        buf ^= 1;
    }
}

extern "C" void kernel_launch(void* const* d_in, const int* in_sizes, int n_in,
                              void* d_out, int out_size)
{
    int E = out_size;  // one score per edge

    const float* x  = nullptr;
    const float* R  = nullptr;
    const void*  ei = nullptr;
    const void*  et = nullptr;
    for (int i = 0; i < n_in; i++) {
        long long sz = in_sizes[i];
        if      (sz == 2LL * E)      ei = d_in[i];
        else if (sz == (long long)E) et = d_in[i];
        else if (sz == 30848LL)      R  = (const float*)d_in[i];
        else                         x  = (const float*)d_in[i];
    }
    if (!x || !R || !ei || !et) {
        x  = (const float*)d_in[0];
        R  = (const float*)d_in[1];
        ei = d_in[2];
        et = d_in[3];
    }

    detect_idx_dtype<<<1, 1>>>(ei);

    int ntiles = (E + 127) / 128;
    int blocks = 148 * 8;                 // persistent: one wave
    if (blocks > ntiles) blocks = ntiles;

    distmult_kernel<<<blocks, 256>>>(x, R, ei, et, (float*)d_out, E, ntiles);
}

// round 10
// speedup vs baseline: 2.7568x; 1.9860x over previous
#include <cuda_runtime.h>
#include <cuda_bf16.h>

// DistMult decoder:
//   out[e] = sigmoid( sum_d x[left[e],d] * R[type[e],d] * x[right[e],d] )
//
// R10: R7 load shape (8 lanes/edge, 4 edges/group, 12 front-batched LDG.128,
// f32x2 packed FMA, launch_bounds(256,8)), but warp-autonomous:
// NO smem, NO __syncthreads. Each warp stages its 16 edges' indices with
// 2 coalesced predicated LDGs and distributes them via shfl.idx.

__device__ int g_idx_is64;

__global__ void detect_idx_dtype(const void* edge_index_raw)
{
    const long long* p = (const long long*)edge_index_raw;
    int is64 = 1;
    #pragma unroll
    for (int i = 0; i < 8; i++) {
        long long v = p[i];
        if (v < 0 || v >= 100000LL) is64 = 0;
    }
    g_idx_is64 = is64;
}

#define PACK2(out_, x_, y_) \
    asm("mov.b64 %0, {%1, %2};" : "=l"(out_) : "f"(x_), "f"(y_))
#define UNPACK2(x_, y_, in_) \
    asm("mov.b64 {%0, %1}, %2;" : "=f"(x_), "=f"(y_) : "l"(in_))
#define MUL2(out_, a_, b_) \
    asm("mul.rn.f32x2 %0, %1, %2;" : "=l"(out_) : "l"(a_), "l"(b_))
#define FMA2(out_, a_, b_, c_) \
    asm("fma.rn.f32x2 %0, %1, %2, %3;" : "=l"(out_) : "l"(a_), "l"(b_), "l"(c_))

// Triple-product partial for one edge on this lane: sum over 4 dims.
__device__ __forceinline__ float triple4(float4 a, float4 c, float4 b)
{
    unsigned long long a0, a1, b0, b1, c0, c1, t, acc;
    PACK2(a0, a.x, a.y); PACK2(a1, a.z, a.w);
    PACK2(b0, b.x, b.y); PACK2(b1, b.z, b.w);
    PACK2(c0, c.x, c.y); PACK2(c1, c.z, c.w);
    MUL2(t, a0, c0);
    MUL2(acc, t, b0);            // acc = a0*c0*b0
    MUL2(t, a1, c1);
    FMA2(acc, t, b1, acc);       // acc += a1*c1*b1
    float lo, hi;
    UNPACK2(lo, hi, acc);
    return lo + hi;
}

__global__ void __launch_bounds__(256, 8) distmult_kernel(
    const float* __restrict__ x,
    const float* __restrict__ R,
    const void* __restrict__ edge_index_raw,
    const void* __restrict__ edge_type_raw,
    float* __restrict__ out,
    int E)
{
    const int tid  = threadIdx.x;
    const int lane = tid & 31;
    const int warp = tid >> 5;

    // This warp owns 16 consecutive edges starting at e0.
    const int e0 = blockIdx.x * 128 + warp * 16;

    // ---- Warp-local index staging: 2 coalesced predicated LDGs ----
    // lr: lanes 0..15 hold left[e0+lane], lanes 16..31 hold right[e0+lane-16].
    // tv: lanes 0..15 hold type[e0+lane] (upper lanes mirror, harmless).
    const int eslot = e0 + (lane & 15);
    const bool ok   = (eslot < E);
    int lr = 0, tv = 0;
    if (g_idx_is64) {
        const long long* ei = (const long long*)edge_index_raw;
        const long long* et = (const long long*)edge_type_raw;
        if (ok) {
            lr = (int)__ldg(ei + (lane < 16 ? eslot : E + eslot));
            tv = (int)__ldg(et + eslot);
        }
    } else {
        const int* ei = (const int*)edge_index_raw;
        const int* et = (const int*)edge_type_raw;
        if (ok) {
            lr = __ldg(ei + (lane < 16 ? eslot : E + eslot));
            tv = __ldg(et + eslot);
        }
    }

    // ---- Distribute indices to 8-lane groups via shfl.idx ----
    const unsigned FULL = 0xffffffffu;
    const int g4  = (lane >> 3) * 4;   // first edge (0..12) of this group
    const int sub = lane & 7;

    const int l0 = __shfl_sync(FULL, lr, g4 + 0);
    const int l1 = __shfl_sync(FULL, lr, g4 + 1);
    const int l2 = __shfl_sync(FULL, lr, g4 + 2);
    const int l3 = __shfl_sync(FULL, lr, g4 + 3);
    const int r0 = __shfl_sync(FULL, lr, 16 + g4 + 0);
    const int r1 = __shfl_sync(FULL, lr, 16 + g4 + 1);
    const int r2 = __shfl_sync(FULL, lr, 16 + g4 + 2);
    const int r3 = __shfl_sync(FULL, lr, 16 + g4 + 3);
    const int t0 = __shfl_sync(FULL, tv, g4 + 0);
    const int t1 = __shfl_sync(FULL, tv, g4 + 1);
    const int t2 = __shfl_sync(FULL, tv, g4 + 2);
    const int t3 = __shfl_sync(FULL, tv, g4 + 3);

    const float4* xb = (const float4*)x;
    const float4* Rb = (const float4*)R;

    // ---- 12 independent row loads (8 lanes x 16 B = one 128 B line) ----
    float4 A0 = __ldg(xb + l0 * 8 + sub);
    float4 B0 = __ldg(xb + r0 * 8 + sub);
    float4 A1 = __ldg(xb + l1 * 8 + sub);
    float4 B1 = __ldg(xb + r1 * 8 + sub);
    float4 A2 = __ldg(xb + l2 * 8 + sub);
    float4 B2 = __ldg(xb + r2 * 8 + sub);
    float4 A3 = __ldg(xb + l3 * 8 + sub);
    float4 B3 = __ldg(xb + r3 * 8 + sub);
    float4 C0 = __ldg(Rb + t0 * 8 + sub);   // near-uniform (sorted types)
    float4 C1 = __ldg(Rb + t1 * 8 + sub);
    float4 C2 = __ldg(Rb + t2 * 8 + sub);
    float4 C3 = __ldg(Rb + t3 * 8 + sub);

    float s0 = triple4(A0, C0, B0);
    float s1 = triple4(A1, C1, B1);
    float s2 = triple4(A2, C2, B2);
    float s3 = triple4(A3, C3, B3);

    // ---- Butterfly reduce over 8 lanes; 4 independent chains ----
    s0 += __shfl_xor_sync(FULL, s0, 4);
    s1 += __shfl_xor_sync(FULL, s1, 4);
    s2 += __shfl_xor_sync(FULL, s2, 4);
    s3 += __shfl_xor_sync(FULL, s3, 4);
    s0 += __shfl_xor_sync(FULL, s0, 2);
    s1 += __shfl_xor_sync(FULL, s1, 2);
    s2 += __shfl_xor_sync(FULL, s2, 2);
    s3 += __shfl_xor_sync(FULL, s3, 2);
    s0 += __shfl_xor_sync(FULL, s0, 1);
    s1 += __shfl_xor_sync(FULL, s1, 1);
    s2 += __shfl_xor_sync(FULL, s2, 1);
    s3 += __shfl_xor_sync(FULL, s3, 1);

    // Lanes 0..3 of each group store edges g4+0..g4+3.
    float v = s0;
    if (sub == 1) v = s1;
    if (sub == 2) v = s2;
    if (sub == 3) v = s3;

    const int e = e0 + g4 + sub;
    if (sub < 4 && e < E) {
        out[e] = __fdividef(1.0f, 1.0f + __expf(-v));
    }
}

extern "C" void kernel_launch(void* const* d_in, const int* in_sizes, int n_in,
                              void* d_out, int out_size)
{
    int E = out_size;  // one score per edge

    const float* x  = nullptr;
    const float* R  = nullptr;
    const void*  ei = nullptr;
    const void*  et = nullptr;
    for (int i = 0; i < n_in; i++) {
        long long sz = in_sizes[i];
        if      (sz == 2LL * E)      ei = d_in[i];
        else if (sz == (long long)E) et = d_in[i];
        else if (sz == 30848LL)      R  = (const float*)d_in[i];
        else                         x  = (const float*)d_in[i];
    }
    if (!x || !R || !ei || !et) {
        x  = (const float*)d_in[0];
        R  = (const float*)d_in[1];
        ei = d_in[2];
        et = d_in[3];
    }

    detect_idx_dtype<<<1, 1>>>(ei);

    int blocks = (E + 127) / 128;
    distmult_kernel<<<blocks, 256>>>(x, R, ei, et, (float*)d_out, E);
}

// round 11
// speedup vs baseline: 2.8079x; 1.0186x over previous
#include <cuda_runtime.h>
#include <cuda_bf16.h>

// DistMult decoder:
//   out[e] = sigmoid( sum_d x[left[e],d] * R[type[e],d] * x[right[e],d] )
//
// R11: warp-autonomous (no __syncthreads), 8 lanes/edge, 4 edges/group,
// 12 front-batched LDG.128 gathers, f32x2 packed FMA, launch_bounds(256,8).
// New vs R10:
//  - warp-private smem index staging: 2 LDG + 1 shfl + STS.128 + 4x LDS.128
//    (replaces 12 shfl.idx + lane math)
//  - transpose-butterfly reduction: 4 shfls + 6 SELs (replaces 12 shfls),
//    result lands directly in the storing lane.

__device__ int g_idx_is64;

__global__ void detect_idx_dtype(const void* edge_index_raw)
{
    const long long* p = (const long long*)edge_index_raw;
    int is64 = 1;
    #pragma unroll
    for (int i = 0; i < 8; i++) {
        long long v = p[i];
        if (v < 0 || v >= 100000LL) is64 = 0;
    }
    g_idx_is64 = is64;
}

#define PACK2(out_, x_, y_) \
    asm("mov.b64 %0, {%1, %2};" : "=l"(out_) : "f"(x_), "f"(y_))
#define UNPACK2(x_, y_, in_) \
    asm("mov.b64 {%0, %1}, %2;" : "=f"(x_), "=f"(y_) : "l"(in_))
#define MUL2(out_, a_, b_) \
    asm("mul.rn.f32x2 %0, %1, %2;" : "=l"(out_) : "l"(a_), "l"(b_))
#define FMA2(out_, a_, b_, c_) \
    asm("fma.rn.f32x2 %0, %1, %2, %3;" : "=l"(out_) : "l"(a_), "l"(b_), "l"(c_))

// Triple-product partial for one edge on this lane: sum over 4 dims.
__device__ __forceinline__ float triple4(float4 a, float4 c, float4 b)
{
    unsigned long long a0, a1, b0, b1, c0, c1, t, acc;
    PACK2(a0, a.x, a.y); PACK2(a1, a.z, a.w);
    PACK2(b0, b.x, b.y); PACK2(b1, b.z, b.w);
    PACK2(c0, c.x, c.y); PACK2(c1, c.z, c.w);
    MUL2(t, a0, c0);
    MUL2(acc, t, b0);            // acc = a0*c0*b0
    MUL2(t, a1, c1);
    FMA2(acc, t, b1, acc);       // acc += a1*c1*b1
    float lo, hi;
    UNPACK2(lo, hi, acc);
    return lo + hi;
}

__global__ void __launch_bounds__(256, 8) distmult_kernel(
    const float* __restrict__ x,
    const float* __restrict__ R,
    const void* __restrict__ edge_index_raw,
    const void* __restrict__ edge_type_raw,
    float* __restrict__ out,
    int E)
{
    __shared__ int4 s_idx[8][16];    // per-warp (l, r, t, 0) for 16 edges

    const int tid  = threadIdx.x;
    const int lane = tid & 31;
    const int warp = tid >> 5;
    const unsigned FULL = 0xffffffffu;

    // This warp owns 16 consecutive edges starting at e0.
    const int e0 = blockIdx.x * 128 + warp * 16;

    // ---- Warp-local index staging: 2 coalesced predicated LDGs ----
    // lr: lanes 0..15 hold left[e0+k], lanes 16..31 hold right[e0+k].
    // tv: lanes 0..15 hold type[e0+k].
    const int eslot = e0 + (lane & 15);
    const bool ok   = (eslot < E);
    int lr = 0, tv = 0;
    if (g_idx_is64) {
        const long long* ei = (const long long*)edge_index_raw;
        const long long* et = (const long long*)edge_type_raw;
        if (ok) {
            lr = (int)__ldg(ei + (lane < 16 ? eslot : E + eslot));
            tv = (int)__ldg(et + eslot);
        }
    } else {
        const int* ei = (const int*)edge_index_raw;
        const int* et = (const int*)edge_type_raw;
        if (ok) {
            lr = __ldg(ei + (lane < 16 ? eslot : E + eslot));
            tv = __ldg(et + eslot);
        }
    }

    // Pair up (l, r): lanes 0..15 fetch their edge's right index from lane+16.
    int rpair = __shfl_xor_sync(FULL, lr, 16);
    if (lane < 16) {
        s_idx[warp][lane] = make_int4(lr, rpair, tv, 0);
    }
    __syncwarp();

    // ---- Each 8-lane group reads its 4 edges' indices: 4x LDS.128 ----
    const int g4  = (lane >> 3) * 4;   // first edge (0,4,8,12) of this group
    const int sub = lane & 7;

    const int4 i0 = s_idx[warp][g4 + 0];
    const int4 i1 = s_idx[warp][g4 + 1];
    const int4 i2 = s_idx[warp][g4 + 2];
    const int4 i3 = s_idx[warp][g4 + 3];

    const float4* xb = (const float4*)x;
    const float4* Rb = (const float4*)R;

    // ---- 12 independent row loads (8 lanes x 16 B = one 128 B line) ----
    float4 A0 = __ldg(xb + i0.x * 8 + sub);
    float4 B0 = __ldg(xb + i0.y * 8 + sub);
    float4 A1 = __ldg(xb + i1.x * 8 + sub);
    float4 B1 = __ldg(xb + i1.y * 8 + sub);
    float4 A2 = __ldg(xb + i2.x * 8 + sub);
    float4 B2 = __ldg(xb + i2.y * 8 + sub);
    float4 A3 = __ldg(xb + i3.x * 8 + sub);
    float4 B3 = __ldg(xb + i3.y * 8 + sub);
    float4 C0 = __ldg(Rb + i0.z * 8 + sub);   // near-uniform (sorted types)
    float4 C1 = __ldg(Rb + i1.z * 8 + sub);
    float4 C2 = __ldg(Rb + i2.z * 8 + sub);
    float4 C3 = __ldg(Rb + i3.z * 8 + sub);

    float s0 = triple4(A0, C0, B0);
    float s1 = triple4(A1, C1, B1);
    float s2 = triple4(A2, C2, B2);
    float s3 = triple4(A3, C3, B3);

    // ---- Transpose-butterfly: reduce 4 values over 8 lanes in 4 shfls ----
    // Stage 1 (xor 1): combine (s0,s1) and (s2,s3) across lane pairs.
    const bool o1 = (sub & 1);
    float a = o1 ? s1 : s0;
    float b = o1 ? s0 : s1;
    a += __shfl_xor_sync(FULL, b, 1);     // even: s0-pair, odd: s1-pair
    float c = o1 ? s3 : s2;
    float d = o1 ? s2 : s3;
    c += __shfl_xor_sync(FULL, d, 1);     // even: s2-pair, odd: s3-pair
    // Stage 2 (xor 2): merge -> lane (sub&3) holds edge (sub&3), 4-lane sum.
    const bool o2 = (sub & 2);
    float e_ = o2 ? c : a;
    float f_ = o2 ? a : c;
    e_ += __shfl_xor_sync(FULL, f_, 2);
    // Stage 3 (xor 4): full 8-lane sum; lane sub holds edge g4 + (sub&3).
    e_ += __shfl_xor_sync(FULL, e_, 4);

    // Lanes 0..3 of each group store edges g4+0..g4+3 directly.
    const int e = e0 + g4 + sub;
    if (sub < 4 && e < E) {
        out[e] = __fdividef(1.0f, 1.0f + __expf(-e_));
    }
}

extern "C" void kernel_launch(void* const* d_in, const int* in_sizes, int n_in,
                              void* d_out, int out_size)
{
    int E = out_size;  // one score per edge

    const float* x  = nullptr;
    const float* R  = nullptr;
    const void*  ei = nullptr;
    const void*  et = nullptr;
    for (int i = 0; i < n_in; i++) {
        long long sz = in_sizes[i];
        if      (sz == 2LL * E)      ei = d_in[i];
        else if (sz == (long long)E) et = d_in[i];
        else if (sz == 30848LL)      R  = (const float*)d_in[i];
        else                         x  = (const float*)d_in[i];
    }
    if (!x || !R || !ei || !et) {
        x  = (const float*)d_in[0];
        R  = (const float*)d_in[1];
        ei = d_in[2];
        et = d_in[3];
    }

    detect_idx_dtype<<<1, 1>>>(ei);

    int blocks = (E + 127) / 128;
    distmult_kernel<<<blocks, 256>>>(x, R, ei, et, (float*)d_out, E);
}

// round 12
// speedup vs baseline: 3.0602x; 1.0898x over previous
#include <cuda_runtime.h>
#include <cuda_bf16.h>

// DistMult decoder:
//   out[e] = sigmoid( sum_d x[left[e],d] * R[type[e],d] * x[right[e],d] )
//
// R12: warp-autonomous, 8 lanes/edge, 4 edges/group, 12 front-batched
// LDG.128 gathers, f32x2 packed FMA, launch_bounds(256,8).
//  - shfl.idx index distribution (no smem, no STS/LDS/syncwarp -> fewer
//    L1 wavefronts; L1 is the binding pipe at ~83%)
//  - transpose-butterfly reduction: 4 shfls, result lands in storing lane.

__device__ int g_idx_is64;

__global__ void detect_idx_dtype(const void* edge_index_raw)
{
    const long long* p = (const long long*)edge_index_raw;
    int is64 = 1;
    #pragma unroll
    for (int i = 0; i < 8; i++) {
        long long v = p[i];
        if (v < 0 || v >= 100000LL) is64 = 0;
    }
    g_idx_is64 = is64;
}

#define PACK2(out_, x_, y_) \
    asm("mov.b64 %0, {%1, %2};" : "=l"(out_) : "f"(x_), "f"(y_))
#define UNPACK2(x_, y_, in_) \
    asm("mov.b64 {%0, %1}, %2;" : "=f"(x_), "=f"(y_) : "l"(in_))
#define MUL2(out_, a_, b_) \
    asm("mul.rn.f32x2 %0, %1, %2;" : "=l"(out_) : "l"(a_), "l"(b_))
#define FMA2(out_, a_, b_, c_) \
    asm("fma.rn.f32x2 %0, %1, %2, %3;" : "=l"(out_) : "l"(a_), "l"(b_), "l"(c_))

// Triple-product partial for one edge on this lane: sum over 4 dims.
__device__ __forceinline__ float triple4(float4 a, float4 c, float4 b)
{
    unsigned long long a0, a1, b0, b1, c0, c1, t, acc;
    PACK2(a0, a.x, a.y); PACK2(a1, a.z, a.w);
    PACK2(b0, b.x, b.y); PACK2(b1, b.z, b.w);
    PACK2(c0, c.x, c.y); PACK2(c1, c.z, c.w);
    MUL2(t, a0, c0);
    MUL2(acc, t, b0);            // acc = a0*c0*b0
    MUL2(t, a1, c1);
    FMA2(acc, t, b1, acc);       // acc += a1*c1*b1
    float lo, hi;
    UNPACK2(lo, hi, acc);
    return lo + hi;
}

__global__ void __launch_bounds__(256, 8) distmult_kernel(
    const float* __restrict__ x,
    const float* __restrict__ R,
    const void* __restrict__ edge_index_raw,
    const void* __restrict__ edge_type_raw,
    float* __restrict__ out,
    int E)
{
    const int tid  = threadIdx.x;
    const int lane = tid & 31;
    const int warp = tid >> 5;
    const unsigned FULL = 0xffffffffu;

    // This warp owns 16 consecutive edges starting at e0.
    const int e0 = blockIdx.x * 128 + warp * 16;

    // ---- Warp-local index staging: 2 coalesced predicated LDGs ----
    // lr: lanes 0..15 hold left[e0+k], lanes 16..31 hold right[e0+k].
    // tv: lanes 0..15 hold type[e0+k] (upper half mirrors, harmless).
    const int eslot = e0 + (lane & 15);
    const bool ok   = (eslot < E);
    int lr = 0, tv = 0;
    if (g_idx_is64) {
        const long long* ei = (const long long*)edge_index_raw;
        const long long* et = (const long long*)edge_type_raw;
        if (ok) {
            lr = (int)__ldg(ei + (lane < 16 ? eslot : E + eslot));
            tv = (int)__ldg(et + eslot);
        }
    } else {
        const int* ei = (const int*)edge_index_raw;
        const int* et = (const int*)edge_type_raw;
        if (ok) {
            lr = __ldg(ei + (lane < 16 ? eslot : E + eslot));
            tv = __ldg(et + eslot);
        }
    }

    // ---- Distribute indices to 8-lane groups via shfl.idx (no smem) ----
    const int g4  = (lane >> 3) * 4;   // first edge (0,4,8,12) of this group
    const int sub = lane & 7;

    const int l0 = __shfl_sync(FULL, lr, g4 + 0);
    const int l1 = __shfl_sync(FULL, lr, g4 + 1);
    const int l2 = __shfl_sync(FULL, lr, g4 + 2);
    const int l3 = __shfl_sync(FULL, lr, g4 + 3);
    const int r0 = __shfl_sync(FULL, lr, 16 + g4 + 0);
    const int r1 = __shfl_sync(FULL, lr, 16 + g4 + 1);
    const int r2 = __shfl_sync(FULL, lr, 16 + g4 + 2);
    const int r3 = __shfl_sync(FULL, lr, 16 + g4 + 3);
    const int t0 = __shfl_sync(FULL, tv, g4 + 0);
    const int t1 = __shfl_sync(FULL, tv, g4 + 1);
    const int t2 = __shfl_sync(FULL, tv, g4 + 2);
    const int t3 = __shfl_sync(FULL, tv, g4 + 3);

    const float4* xb = (const float4*)x;
    const float4* Rb = (const float4*)R;

    // ---- 12 independent row loads (8 lanes x 16 B = one 128 B line) ----
    float4 A0 = __ldg(xb + l0 * 8 + sub);
    float4 B0 = __ldg(xb + r0 * 8 + sub);
    float4 A1 = __ldg(xb + l1 * 8 + sub);
    float4 B1 = __ldg(xb + r1 * 8 + sub);
    float4 A2 = __ldg(xb + l2 * 8 + sub);
    float4 B2 = __ldg(xb + r2 * 8 + sub);
    float4 A3 = __ldg(xb + l3 * 8 + sub);
    float4 B3 = __ldg(xb + r3 * 8 + sub);
    float4 C0 = __ldg(Rb + t0 * 8 + sub);   // near-uniform (sorted types)
    float4 C1 = __ldg(Rb + t1 * 8 + sub);
    float4 C2 = __ldg(Rb + t2 * 8 + sub);
    float4 C3 = __ldg(Rb + t3 * 8 + sub);

    float s0 = triple4(A0, C0, B0);
    float s1 = triple4(A1, C1, B1);
    float s2 = triple4(A2, C2, B2);
    float s3 = triple4(A3, C3, B3);

    // ---- Transpose-butterfly: reduce 4 values over 8 lanes in 4 shfls ----
    // Stage 1 (xor 1): combine (s0,s1) and (s2,s3) across lane pairs.
    const bool o1 = (sub & 1);
    float a = o1 ? s1 : s0;
    float b = o1 ? s0 : s1;
    a += __shfl_xor_sync(FULL, b, 1);     // even: s0-pair, odd: s1-pair
    float c = o1 ? s3 : s2;
    float d = o1 ? s2 : s3;
    c += __shfl_xor_sync(FULL, d, 1);     // even: s2-pair, odd: s3-pair
    // Stage 2 (xor 2): lane (sub&3) holds edge (sub&3), 4-lane partial.
    const bool o2 = (sub & 2);
    float e_ = o2 ? c : a;
    float f_ = o2 ? a : c;
    e_ += __shfl_xor_sync(FULL, f_, 2);
    // Stage 3 (xor 4): full 8-lane sum; lane sub holds edge g4 + (sub&3).
    e_ += __shfl_xor_sync(FULL, e_, 4);

    // Lanes 0..3 of each group store edges g4+0..g4+3 directly.
    const int e = e0 + g4 + sub;
    if (sub < 4 && e < E) {
        out[e] = __fdividef(1.0f, 1.0f + __expf(-e_));
    }
}

extern "C" void kernel_launch(void* const* d_in, const int* in_sizes, int n_in,
                              void* d_out, int out_size)
{
    int E = out_size;  // one score per edge

    const float* x  = nullptr;
    const float* R  = nullptr;
    const void*  ei = nullptr;
    const void*  et = nullptr;
    for (int i = 0; i < n_in; i++) {
        long long sz = in_sizes[i];
        if      (sz == 2LL * E)      ei = d_in[i];
        else if (sz == (long long)E) et = d_in[i];
        else if (sz == 30848LL)      R  = (const float*)d_in[i];
        else                         x  = (const float*)d_in[i];
    }
    if (!x || !R || !ei || !et) {
        x  = (const float*)d_in[0];
        R  = (const float*)d_in[1];
        ei = d_in[2];
        et = d_in[3];
    }

    detect_idx_dtype<<<1, 1>>>(ei);

    int blocks = (E + 127) / 128;
    distmult_kernel<<<blocks, 256>>>(x, R, ei, et, (float*)d_out, E);
}